// round 1
// baseline (speedup 1.0000x reference)
#include <cuda_runtime.h>
#include <math.h>

// Problem constants
#define NB   2      // batch
#define IH   128
#define IW   128
#define IC   192
#define DH   64     // downsampled H=W
#define LTOT 4096   // 64*64 patch/query count
#define NWR  3072   // 16 * 192  (4x4 kernel taps * C)

// ---------------- scratch (device globals; allocation-free) ----------------
__device__ float g_fd[NB][LTOT][IC];                 // downsampled f, packed [p][c]
__device__ float g_bd[NB][LTOT][IC];                 // downsampled b
__device__ float g_n2[NB][LTOT];                     // per-pixel sum of squares of bd
__device__ float g_norm[NB][LTOT];                   // patch norms
__device__ float g_mm[LTOT];                         // valid-patch mask
__device__ float g_D[NB][(size_t)LTOT * LTOT];       // pixel-dot matrix / fuse temp
__device__ float g_S[NB][(size_t)LTOT * LTOT];       // scores / softmax (in place)
__device__ float g_Wr[NB][(size_t)LTOT * NWR];       // raw patch matrix (deconv B)
__device__ float g_Out[NB][(size_t)LTOT * NWR];      // deconv GEMM result

// ---------------- K1: downsample + pack + per-pixel |bd|^2 ----------------
__global__ void k_pack(const float* __restrict__ f, const float* __restrict__ b) {
    int i = blockIdx.z;
    int p = blockIdx.x;                 // 0..4095 downsampled pixel
    int x = p >> 6, y = p & 63;
    size_t base = (((size_t)i * IH + 2 * x) * IW + 2 * y) * IC;
    int c = threadIdx.x;                // 0..191
    float fv = f[base + c];
    float bv = b[base + c];
    g_fd[i][p][c] = fv;
    g_bd[i][p][c] = bv;

    __shared__ float sh[192];
    sh[c] = bv * bv;
    __syncthreads();
    if (c < 64) sh[c] += sh[c + 64] + sh[c + 128];
    __syncthreads();
    if (c < 32) {
        float v = sh[c] + sh[c + 32];
        #pragma unroll
        for (int o = 16; o > 0; o >>= 1) v += __shfl_down_sync(0xffffffffu, v, o);
        if (c == 0) g_n2[i][p] = v;
    }
}

// ---------------- K1b: patch norms (3x3 stencil of n2) + mask mm ----------
__global__ void k_norm_mm(const float* __restrict__ mask) {
    int i = blockIdx.z;
    int l = blockIdx.x * 128 + threadIdx.x;   // 0..4095
    int u = l >> 6, v = l & 63;
    float s = 0.f;
    #pragma unroll
    for (int a = -1; a <= 1; ++a)
        #pragma unroll
        for (int bo = -1; bo <= 1; ++bo) {
            int uu = u + a, vv = v + bo;
            if ((unsigned)uu < 64u && (unsigned)vv < 64u)
                s += g_n2[i][uu * 64 + vv];
        }
    g_norm[i][l] = fmaxf(sqrtf(s), 1e-4f);

    if (i == 0) {
        float ms = 0.f;
        #pragma unroll
        for (int a = -1; a <= 1; ++a)
            #pragma unroll
            for (int bo = -1; bo <= 1; ++bo) {
                int uu = u + a, vv = v + bo;
                if ((unsigned)uu < 64u && (unsigned)vv < 64u)
                    ms += mask[(2 * uu) * IW + 2 * vv];
            }
        g_mm[l] = (ms == 0.0f) ? 1.0f : 0.0f;
    }
}

// ---------------- K2: D = fd * bd^T  (NT GEMM, M=N=4096, K=192) -----------
__global__ __launch_bounds__(256, 2)
void k_gemm_D() {
    int i = blockIdx.z;
    const float* A = &g_fd[i][0][0];
    const float* B = &g_bd[i][0][0];
    float* Cm = g_D[i];
    __shared__ float As[8][132];
    __shared__ float Bs[8][132];
    int bm = blockIdx.y << 7, bn = blockIdx.x << 7;
    int t = threadIdx.x, tx = t & 15, ty = t >> 4;
    int lrow = t >> 1, lkq = (t & 1) << 2;
    float acc[8][8] = {};

    for (int k0 = 0; k0 < 192; k0 += 8) {
        float4 av = *(const float4*)(A + (size_t)(bm + lrow) * 192 + k0 + lkq);
        float4 bv = *(const float4*)(B + (size_t)(bn + lrow) * 192 + k0 + lkq);
        As[lkq + 0][lrow] = av.x; As[lkq + 1][lrow] = av.y;
        As[lkq + 2][lrow] = av.z; As[lkq + 3][lrow] = av.w;
        Bs[lkq + 0][lrow] = bv.x; Bs[lkq + 1][lrow] = bv.y;
        Bs[lkq + 2][lrow] = bv.z; Bs[lkq + 3][lrow] = bv.w;
        __syncthreads();
        #pragma unroll
        for (int kk = 0; kk < 8; ++kk) {
            float ar[8], br[8];
            *(float4*)&ar[0] = *(const float4*)&As[kk][ty * 8];
            *(float4*)&ar[4] = *(const float4*)&As[kk][ty * 8 + 4];
            *(float4*)&br[0] = *(const float4*)&Bs[kk][tx * 8];
            *(float4*)&br[4] = *(const float4*)&Bs[kk][tx * 8 + 4];
            #pragma unroll
            for (int m = 0; m < 8; ++m)
                #pragma unroll
                for (int n = 0; n < 8; ++n)
                    acc[m][n] = fmaf(ar[m], br[n], acc[m][n]);
        }
        __syncthreads();
    }
    #pragma unroll
    for (int m = 0; m < 8; ++m) {
        float* dst = Cm + (size_t)(bm + ty * 8 + m) * 4096 + bn + tx * 8;
        *(float4*)dst       = make_float4(acc[m][0], acc[m][1], acc[m][2], acc[m][3]);
        *(float4*)(dst + 4) = make_float4(acc[m][4], acc[m][5], acc[m][6], acc[m][7]);
    }
}

// ---------------- K3: S[q,l] = 9-tap diagonal stencil of D / norm[l] ------
__global__ void k_score() {
    int i = blockIdx.z;
    int idx = blockIdx.x * 256 + threadIdx.x;    // < 16777216
    int q = idx >> 12, l = idx & 4095;
    int x = q >> 6, y = q & 63, u = l >> 6, v = l & 63;
    const float* D = g_D[i];
    float s = 0.f;
    #pragma unroll
    for (int a = -1; a <= 1; ++a) {
        if ((unsigned)(x + a) < 64u && (unsigned)(u + a) < 64u) {
            #pragma unroll
            for (int bo = -1; bo <= 1; ++bo) {
                if ((unsigned)(y + bo) < 64u && (unsigned)(v + bo) < 64u) {
                    int off = a * 64 + bo;
                    s += D[(size_t)(q + off) * 4096 + (l + off)];
                }
            }
        }
    }
    g_S[i][(size_t)q * 4096 + l] = s / g_norm[i][l];
}

// ---------------- K4: fuse pass 1 (flat-index diagonal, S -> D) -----------
__global__ void k_fuse1() {
    int i = blockIdx.z;
    int idx = blockIdx.x * 256 + threadIdx.x;
    int p = idx >> 12, q = idx & 4095;
    const float* S = g_S[i];
    float s = 0.f;
    #pragma unroll
    for (int d = -1; d <= 1; ++d) {
        int pp = p + d, qq = q + d;
        if ((unsigned)pp < 4096u && (unsigned)qq < 4096u)
            s += S[(size_t)pp * 4096 + qq];
    }
    g_D[i][(size_t)p * 4096 + q] = s;
}

// ------- K5: fuse pass 2 (transposed flattening, D(F1) -> S(final)) -------
__global__ void k_fuse2() {
    int i = blockIdx.z;
    int idx = blockIdx.x * 256 + threadIdx.x;
    int q = idx >> 12, l = idx & 4095;        // q=(i_,j_) row-major h,w; l=(ib,jb)
    int i_ = q >> 6, j_ = q & 63;
    int ib = l >> 6, jb = l & 63;
    int pt = j_ * 64 + i_;                    // transposed flat index
    int qt = jb * 64 + ib;
    const float* F1 = g_D[i];
    float s = 0.f;
    #pragma unroll
    for (int d = -1; d <= 1; ++d) {
        int p2 = pt + d, q2 = qt + d;
        if ((unsigned)p2 < 4096u && (unsigned)q2 < 4096u) {
            int i2 = p2 & 63, j2 = p2 >> 6;   // p2 = j'*64 + i'
            int ib2 = q2 & 63, jb2 = q2 >> 6;
            s += F1[(size_t)(i2 * 64 + j2) * 4096 + (ib2 * 64 + jb2)];
        }
    }
    g_S[i][(size_t)q * 4096 + l] = s;
}

// ---------------- K6: masked softmax over l (in place on g_S) -------------
__global__ void k_softmax() {
    int i = blockIdx.z, q = blockIdx.x;
    float* row = g_S[i] + (size_t)q * 4096;
    int t = threadIdx.x;   // 256
    float vals[16];
    float mx = -3.4e38f;
    #pragma unroll
    for (int j = 0; j < 16; ++j) {
        int l = t + j * 256;
        float v = row[l] * g_mm[l] * 10.0f;
        vals[j] = v;
        mx = fmaxf(mx, v);
    }
    __shared__ float sh[256];
    sh[t] = mx; __syncthreads();
    #pragma unroll
    for (int s = 128; s > 0; s >>= 1) { if (t < s) sh[t] = fmaxf(sh[t], sh[t + s]); __syncthreads(); }
    mx = sh[0];
    __syncthreads();
    float sum = 0.f;
    #pragma unroll
    for (int j = 0; j < 16; ++j) { vals[j] = expf(vals[j] - mx); sum += vals[j]; }
    sh[t] = sum; __syncthreads();
    #pragma unroll
    for (int s = 128; s > 0; s >>= 1) { if (t < s) sh[t] += sh[t + s]; __syncthreads(); }
    float inv = 1.0f / sh[0];
    #pragma unroll
    for (int j = 0; j < 16; ++j) {
        int l = t + j * 256;
        row[l] = vals[j] * inv * g_mm[l];
    }
}

// ---------------- K7: pack raw patch matrix Wr[l][(kx,ky,c)] --------------
__global__ void k_packWr(const float* __restrict__ b) {
    int i = blockIdx.z;
    int idx = blockIdx.x * 256 + threadIdx.x;   // < 4096*3072
    int l = idx / NWR, n = idx - l * NWR;
    int u = l >> 6, v = l & 63;
    int kk = n / IC, c = n - kk * IC;
    int kx = kk >> 2, ky = kk & 3;
    int X = 2 * u + kx - 1, Y = 2 * v + ky - 1;
    float val = 0.f;
    if ((unsigned)X < 128u && (unsigned)Y < 128u)
        val = b[(((size_t)i * IH + X) * IW + Y) * IC + c];
    g_Wr[i][(size_t)l * NWR + n] = val;
}

// ------- K8: Out = A(softmax, 4096x4096) * Wr(4096x3072)  (NN GEMM) -------
__global__ __launch_bounds__(256, 2)
void k_gemm_out() {
    int i = blockIdx.z;
    const float* A = g_S[i];
    const float* B = g_Wr[i];
    float* Cm = g_Out[i];
    __shared__ float As[8][132];
    __shared__ float Bs[8][132];
    int bm = blockIdx.y << 7, bn = blockIdx.x << 7;
    int t = threadIdx.x, tx = t & 15, ty = t >> 4;
    int arow = t >> 1, akq = (t & 1) << 2;
    int bkr = t >> 5, bnc = (t & 31) << 2;
    float acc[8][8] = {};

    for (int k0 = 0; k0 < 4096; k0 += 8) {
        float4 av = *(const float4*)(A + (size_t)(bm + arow) * 4096 + k0 + akq);
        float4 bv = *(const float4*)(B + (size_t)(k0 + bkr) * 3072 + bn + bnc);
        As[akq + 0][arow] = av.x; As[akq + 1][arow] = av.y;
        As[akq + 2][arow] = av.z; As[akq + 3][arow] = av.w;
        *(float4*)&Bs[bkr][bnc] = bv;
        __syncthreads();
        #pragma unroll
        for (int kk = 0; kk < 8; ++kk) {
            float ar[8], br[8];
            *(float4*)&ar[0] = *(const float4*)&As[kk][ty * 8];
            *(float4*)&ar[4] = *(const float4*)&As[kk][ty * 8 + 4];
            *(float4*)&br[0] = *(const float4*)&Bs[kk][tx * 8];
            *(float4*)&br[4] = *(const float4*)&Bs[kk][tx * 8 + 4];
            #pragma unroll
            for (int m = 0; m < 8; ++m)
                #pragma unroll
                for (int n = 0; n < 8; ++n)
                    acc[m][n] = fmaf(ar[m], br[n], acc[m][n]);
        }
        __syncthreads();
    }
    #pragma unroll
    for (int m = 0; m < 8; ++m) {
        float* dst = Cm + (size_t)(bm + ty * 8 + m) * 3072 + bn + tx * 8;
        *(float4*)dst       = make_float4(acc[m][0], acc[m][1], acc[m][2], acc[m][3]);
        *(float4*)(dst + 4) = make_float4(acc[m][4], acc[m][5], acc[m][6], acc[m][7]);
    }
}

// ---------------- K9: parity gather (transpose-conv scatter as gather) ----
__global__ void k_output(float* __restrict__ out) {
    int i = blockIdx.z;
    int idx = blockIdx.x * 256 + threadIdx.x;   // < 128*128*192
    int c = idx % IC;
    int rest = idx / IC;
    int Y = rest % IW, X = rest / IW;
    const float* O = g_Out[i];
    float s = 0.f;
    int rx = (X + 1) & 1, ry = (Y + 1) & 1;
    #pragma unroll
    for (int a = 0; a < 2; ++a) {
        int kx = rx + 2 * a;
        int u = (X + 1 - kx) >> 1;
        if ((unsigned)u < 64u) {
            #pragma unroll
            for (int bo = 0; bo < 2; ++bo) {
                int ky = ry + 2 * bo;
                int v = (Y + 1 - ky) >> 1;
                if ((unsigned)v < 64u)
                    s += O[(size_t)(u * 64 + v) * NWR + (kx * 4 + ky) * IC + c];
            }
        }
    }
    out[(size_t)i * (IH * IW * IC) + idx] = 0.25f * s;
}

// ---------------- launch --------------------------------------------------
extern "C" void kernel_launch(void* const* d_in, const int* in_sizes, int n_in,
                              void* d_out, int out_size) {
    const float* f    = (const float*)d_in[0];
    const float* b    = (const float*)d_in[1];
    const float* mask = (const float*)d_in[2];
    float* out = (float*)d_out;

    k_pack    <<<dim3(4096, 1, NB), 192>>>(f, b);
    k_norm_mm <<<dim3(32,   1, NB), 128>>>(mask);
    k_gemm_D  <<<dim3(32,  32, NB), 256>>>();
    k_score   <<<dim3(65536,1, NB), 256>>>();
    k_fuse1   <<<dim3(65536,1, NB), 256>>>();
    k_fuse2   <<<dim3(65536,1, NB), 256>>>();
    k_softmax <<<dim3(4096, 1, NB), 256>>>();
    k_packWr  <<<dim3(49152,1, NB), 256>>>(b);
    k_gemm_out<<<dim3(24,  32, NB), 256>>>();
    k_output  <<<dim3(12288,1, NB), 256>>>(out);
}

// round 2
// speedup vs baseline: 2.3516x; 2.3516x over previous
#include <cuda_runtime.h>
#include <math.h>

// Problem constants
#define NB   2      // batch
#define IH   128
#define IW   128
#define IC   192
#define LTOT 4096   // 64*64 patch/query count
#define MQ   4225   // 65*65 extended query/source grid
#define MQP  4352   // padded to 34*128
#define NOUT 768    // 4 parities * 192 channels

// ---------------- scratch (device globals; allocation-free) ----------------
__device__ float g_fd[NB][LTOT][IC];                 // downsampled f, packed [p][c]
__device__ float g_bd[NB][LTOT][IC];                 // downsampled b
__device__ float g_n2[NB][LTOT];                     // per-pixel sum of squares of bd
__device__ float g_norm[NB][LTOT];                   // patch norms
__device__ float g_mm[LTOT];                         // valid-patch mask
__device__ float g_D[NB][(size_t)LTOT * LTOT];       // pixel-dot matrix / fuse temp
__device__ float g_S[NB][(size_t)LTOT * LTOT];       // scores / softmax (in place)
__device__ float g_At[NB][(size_t)MQP * MQP];        // folded attention (A-tilde), padded
__device__ float g_Bp[NB][(size_t)MQP * NOUT];       // parity-gathered b (GEMM B), padded rows
__device__ float g_On[NB][(size_t)MQP * NOUT];       // final GEMM result

// ---------------- K1: downsample + pack + per-pixel |bd|^2 ----------------
__global__ void k_pack(const float* __restrict__ f, const float* __restrict__ b) {
    int i = blockIdx.z;
    int p = blockIdx.x;                 // 0..4095 downsampled pixel
    int x = p >> 6, y = p & 63;
    size_t base = (((size_t)i * IH + 2 * x) * IW + 2 * y) * IC;
    int c = threadIdx.x;                // 0..191
    float fv = f[base + c];
    float bv = b[base + c];
    g_fd[i][p][c] = fv;
    g_bd[i][p][c] = bv;

    __shared__ float sh[192];
    sh[c] = bv * bv;
    __syncthreads();
    if (c < 64) sh[c] += sh[c + 64] + sh[c + 128];
    __syncthreads();
    if (c < 32) {
        float v = sh[c] + sh[c + 32];
        #pragma unroll
        for (int o = 16; o > 0; o >>= 1) v += __shfl_down_sync(0xffffffffu, v, o);
        if (c == 0) g_n2[i][p] = v;
    }
}

// ---------------- K1b: patch norms (3x3 stencil of n2) + mask mm ----------
__global__ void k_norm_mm(const float* __restrict__ mask) {
    int i = blockIdx.z;
    int l = blockIdx.x * 128 + threadIdx.x;   // 0..4095
    int u = l >> 6, v = l & 63;
    float s = 0.f;
    #pragma unroll
    for (int a = -1; a <= 1; ++a)
        #pragma unroll
        for (int bo = -1; bo <= 1; ++bo) {
            int uu = u + a, vv = v + bo;
            if ((unsigned)uu < 64u && (unsigned)vv < 64u)
                s += g_n2[i][uu * 64 + vv];
        }
    g_norm[i][l] = fmaxf(sqrtf(s), 1e-4f);

    if (i == 0) {
        float ms = 0.f;
        #pragma unroll
        for (int a = -1; a <= 1; ++a)
            #pragma unroll
            for (int bo = -1; bo <= 1; ++bo) {
                int uu = u + a, vv = v + bo;
                if ((unsigned)uu < 64u && (unsigned)vv < 64u)
                    ms += mask[(2 * uu) * IW + 2 * vv];
            }
        g_mm[l] = (ms == 0.0f) ? 1.0f : 0.0f;
    }
}

// ---------------- K2: D = fd * bd^T  (NT GEMM, M=N=4096, K=192) -----------
__global__ __launch_bounds__(256, 2)
void k_gemm_D() {
    int i = blockIdx.z;
    const float* A = &g_fd[i][0][0];
    const float* B = &g_bd[i][0][0];
    float* Cm = g_D[i];
    __shared__ float As[8][132];
    __shared__ float Bs[8][132];
    int bm = blockIdx.y << 7, bn = blockIdx.x << 7;
    int t = threadIdx.x, tx = t & 15, ty = t >> 4;
    int lrow = t >> 1, lkq = (t & 1) << 2;
    float acc[8][8] = {};

    for (int k0 = 0; k0 < 192; k0 += 8) {
        float4 av = *(const float4*)(A + (size_t)(bm + lrow) * 192 + k0 + lkq);
        float4 bv = *(const float4*)(B + (size_t)(bn + lrow) * 192 + k0 + lkq);
        As[lkq + 0][lrow] = av.x; As[lkq + 1][lrow] = av.y;
        As[lkq + 2][lrow] = av.z; As[lkq + 3][lrow] = av.w;
        Bs[lkq + 0][lrow] = bv.x; Bs[lkq + 1][lrow] = bv.y;
        Bs[lkq + 2][lrow] = bv.z; Bs[lkq + 3][lrow] = bv.w;
        __syncthreads();
        #pragma unroll
        for (int kk = 0; kk < 8; ++kk) {
            float ar[8], br[8];
            *(float4*)&ar[0] = *(const float4*)&As[kk][ty * 8];
            *(float4*)&ar[4] = *(const float4*)&As[kk][ty * 8 + 4];
            *(float4*)&br[0] = *(const float4*)&Bs[kk][tx * 8];
            *(float4*)&br[4] = *(const float4*)&Bs[kk][tx * 8 + 4];
            #pragma unroll
            for (int m = 0; m < 8; ++m)
                #pragma unroll
                for (int n = 0; n < 8; ++n)
                    acc[m][n] = fmaf(ar[m], br[n], acc[m][n]);
        }
        __syncthreads();
    }
    #pragma unroll
    for (int m = 0; m < 8; ++m) {
        float* dst = Cm + (size_t)(bm + ty * 8 + m) * 4096 + bn + tx * 8;
        *(float4*)dst       = make_float4(acc[m][0], acc[m][1], acc[m][2], acc[m][3]);
        *(float4*)(dst + 4) = make_float4(acc[m][4], acc[m][5], acc[m][6], acc[m][7]);
    }
}

// ---------------- K3: S[q,l] = 9-tap diagonal stencil of D / norm[l] ------
__global__ void k_score() {
    int i = blockIdx.z;
    int idx = blockIdx.x * 256 + threadIdx.x;    // < 16777216
    int q = idx >> 12, l = idx & 4095;
    int x = q >> 6, y = q & 63, u = l >> 6, v = l & 63;
    const float* D = g_D[i];
    float s = 0.f;
    #pragma unroll
    for (int a = -1; a <= 1; ++a) {
        if ((unsigned)(x + a) < 64u && (unsigned)(u + a) < 64u) {
            #pragma unroll
            for (int bo = -1; bo <= 1; ++bo) {
                if ((unsigned)(y + bo) < 64u && (unsigned)(v + bo) < 64u) {
                    int off = a * 64 + bo;
                    s += D[(size_t)(q + off) * 4096 + (l + off)];
                }
            }
        }
    }
    g_S[i][(size_t)q * 4096 + l] = s / g_norm[i][l];
}

// ---------------- K4: fuse pass 1 (flat-index diagonal, S -> D) -----------
__global__ void k_fuse1() {
    int i = blockIdx.z;
    int idx = blockIdx.x * 256 + threadIdx.x;
    int p = idx >> 12, q = idx & 4095;
    const float* S = g_S[i];
    float s = 0.f;
    #pragma unroll
    for (int d = -1; d <= 1; ++d) {
        int pp = p + d, qq = q + d;
        if ((unsigned)pp < 4096u && (unsigned)qq < 4096u)
            s += S[(size_t)pp * 4096 + qq];
    }
    g_D[i][(size_t)p * 4096 + q] = s;
}

// ------- K5: fuse pass 2 (transposed flattening, D(F1) -> S(final)) -------
__global__ void k_fuse2() {
    int i = blockIdx.z;
    int idx = blockIdx.x * 256 + threadIdx.x;
    int q = idx >> 12, l = idx & 4095;        // q=(i_,j_) row-major h,w; l=(ib,jb)
    int i_ = q >> 6, j_ = q & 63;
    int ib = l >> 6, jb = l & 63;
    int pt = j_ * 64 + i_;                    // transposed flat index
    int qt = jb * 64 + ib;
    const float* F1 = g_D[i];
    float s = 0.f;
    #pragma unroll
    for (int d = -1; d <= 1; ++d) {
        int p2 = pt + d, q2 = qt + d;
        if ((unsigned)p2 < 4096u && (unsigned)q2 < 4096u) {
            int i2 = p2 & 63, j2 = p2 >> 6;   // p2 = j'*64 + i'
            int ib2 = q2 & 63, jb2 = q2 >> 6;
            s += F1[(size_t)(i2 * 64 + j2) * 4096 + (ib2 * 64 + jb2)];
        }
    }
    g_S[i][(size_t)q * 4096 + l] = s;
}

// ---------------- K6: masked softmax over l (in place on g_S) -------------
__global__ void k_softmax() {
    int i = blockIdx.z, q = blockIdx.x;
    float* row = g_S[i] + (size_t)q * 4096;
    int t = threadIdx.x;   // 256
    float vals[16];
    float mx = -3.4e38f;
    #pragma unroll
    for (int j = 0; j < 16; ++j) {
        int l = t + j * 256;
        float v = row[l] * g_mm[l] * 10.0f;
        vals[j] = v;
        mx = fmaxf(mx, v);
    }
    __shared__ float sh[256];
    sh[t] = mx; __syncthreads();
    #pragma unroll
    for (int s = 128; s > 0; s >>= 1) { if (t < s) sh[t] = fmaxf(sh[t], sh[t + s]); __syncthreads(); }
    mx = sh[0];
    __syncthreads();
    float sum = 0.f;
    #pragma unroll
    for (int j = 0; j < 16; ++j) { vals[j] = expf(vals[j] - mx); sum += vals[j]; }
    sh[t] = sum; __syncthreads();
    #pragma unroll
    for (int s = 128; s > 0; s >>= 1) { if (t < s) sh[t] += sh[t + s]; __syncthreads(); }
    float inv = 1.0f / sh[0];
    #pragma unroll
    for (int j = 0; j < 16; ++j) {
        int l = t + j * 256;
        row[l] = vals[j] * inv * g_mm[l];
    }
}

// ------ K7: build A-tilde: 4-term shifted sum of softmaxed A --------------
// At[(x0,y0),(u',v')] = sum_{a,b in {0,1}} A[(x0-a,y0-b),(u'-a,v'-b)] (OOB->0)
__global__ void k_Abuild() {
    int i = blockIdx.z;
    int q0 = blockIdx.y;                       // 0..4224
    int lp = blockIdx.x * 256 + threadIdx.x;   // 0..4351
    if (lp >= MQ) return;
    int x0 = q0 / 65, y0 = q0 % 65;
    int up = lp / 65, vp = lp % 65;
    const float* A = g_S[i];
    float s = 0.f;
    #pragma unroll
    for (int a = 0; a < 2; ++a) {
        int xr = x0 - a, ur = up - a;
        if ((unsigned)xr < 64u && (unsigned)ur < 64u) {
            #pragma unroll
            for (int bo = 0; bo < 2; ++bo) {
                int yr = y0 - bo, vr = vp - bo;
                if ((unsigned)yr < 64u && (unsigned)vr < 64u)
                    s += A[(size_t)(xr * 64 + yr) * 4096 + (ur * 64 + vr)];
            }
        }
    }
    g_At[i][(size_t)q0 * MQP + lp] = s;
}

// ------ K8: build parity-gathered B: Bp[l'][(par,c)] = b[2u'+rx-1,2v'+ry-1,c]
__global__ void k_Bbuild(const float* __restrict__ b) {
    int i = blockIdx.z;
    int idx = blockIdx.x * 256 + threadIdx.x;   // < 4225*768
    if (idx >= MQ * NOUT) return;
    int lp = idx / NOUT, n = idx - lp * NOUT;
    int par = n / IC, c = n - par * IC;
    int rx = par >> 1, ry = par & 1;
    int up = lp / 65, vp = lp % 65;
    int X = 2 * up + rx - 1, Y = 2 * vp + ry - 1;
    float val = 0.f;
    if ((unsigned)X < 128u && (unsigned)Y < 128u)
        val = b[(((size_t)i * IH + X) * IW + Y) * IC + c];
    g_Bp[i][(size_t)lp * NOUT + n] = val;
}

// ------ K9: On = At(4352x4352) * Bp(4352x768)   (NN GEMM) -----------------
__global__ __launch_bounds__(256, 2)
void k_gemm_out() {
    int i = blockIdx.z;
    const float* A = g_At[i];
    const float* B = g_Bp[i];
    float* Cm = g_On[i];
    __shared__ float As[8][132];
    __shared__ float Bs[8][132];
    int bm = blockIdx.y << 7, bn = blockIdx.x << 7;
    int t = threadIdx.x, tx = t & 15, ty = t >> 4;
    int arow = t >> 1, akq = (t & 1) << 2;
    int bkr = t >> 5, bnc = (t & 31) << 2;
    float acc[8][8] = {};

    for (int k0 = 0; k0 < MQP; k0 += 8) {
        float4 av = *(const float4*)(A + (size_t)(bm + arow) * MQP + k0 + akq);
        float4 bv = *(const float4*)(B + (size_t)(k0 + bkr) * NOUT + bn + bnc);
        As[akq + 0][arow] = av.x; As[akq + 1][arow] = av.y;
        As[akq + 2][arow] = av.z; As[akq + 3][arow] = av.w;
        *(float4*)&Bs[bkr][bnc] = bv;
        __syncthreads();
        #pragma unroll
        for (int kk = 0; kk < 8; ++kk) {
            float ar[8], br[8];
            *(float4*)&ar[0] = *(const float4*)&As[kk][ty * 8];
            *(float4*)&ar[4] = *(const float4*)&As[kk][ty * 8 + 4];
            *(float4*)&br[0] = *(const float4*)&Bs[kk][tx * 8];
            *(float4*)&br[4] = *(const float4*)&Bs[kk][tx * 8 + 4];
            #pragma unroll
            for (int m = 0; m < 8; ++m)
                #pragma unroll
                for (int n = 0; n < 8; ++n)
                    acc[m][n] = fmaf(ar[m], br[n], acc[m][n]);
        }
        __syncthreads();
    }
    #pragma unroll
    for (int m = 0; m < 8; ++m) {
        float* dst = Cm + (size_t)(bm + ty * 8 + m) * NOUT + bn + tx * 8;
        *(float4*)dst       = make_float4(acc[m][0], acc[m][1], acc[m][2], acc[m][3]);
        *(float4*)(dst + 4) = make_float4(acc[m][4], acc[m][5], acc[m][6], acc[m][7]);
    }
}

// ---------------- K10: final parity gather -> output ----------------------
__global__ void k_output(float* __restrict__ out) {
    int i = blockIdx.z;
    int idx = blockIdx.x * 256 + threadIdx.x;   // < 128*128*192
    int c = idx % IC;
    int rest = idx / IC;
    int Y = rest % IW, X = rest / IW;
    int rx = (X + 1) & 1, ry = (Y + 1) & 1;
    int x0 = (X + 1 - rx) >> 1, y0 = (Y + 1 - ry) >> 1;
    float v = g_On[i][(size_t)(x0 * 65 + y0) * NOUT + ((rx << 1) | ry) * IC + c];
    out[(size_t)i * (IH * IW * IC) + idx] = 0.25f * v;
}

// ---------------- launch --------------------------------------------------
extern "C" void kernel_launch(void* const* d_in, const int* in_sizes, int n_in,
                              void* d_out, int out_size) {
    const float* f    = (const float*)d_in[0];
    const float* b    = (const float*)d_in[1];
    const float* mask = (const float*)d_in[2];
    float* out = (float*)d_out;

    k_pack    <<<dim3(4096, 1, NB), 192>>>(f, b);
    k_norm_mm <<<dim3(32,   1, NB), 128>>>(mask);
    k_gemm_D  <<<dim3(32,  32, NB), 256>>>();
    k_score   <<<dim3(65536,1, NB), 256>>>();
    k_fuse1   <<<dim3(65536,1, NB), 256>>>();
    k_fuse2   <<<dim3(65536,1, NB), 256>>>();
    k_softmax <<<dim3(4096, 1, NB), 256>>>();
    k_Abuild  <<<dim3(17, MQ, NB), 256>>>();
    k_Bbuild  <<<dim3((MQ * NOUT + 255) / 256, 1, NB), 256>>>(b);
    k_gemm_out<<<dim3(6,  34, NB), 256>>>();
    k_output  <<<dim3(12288, 1, NB), 256>>>(out);
}